// round 2
// baseline (speedup 1.0000x reference)
#include <cuda_runtime.h>
#include <cstdint>

// MLP: x[N,16] -> L1(16->32)+BN+ReLU -> L2(32->32)+BN+ReLU -> L3(32->32)+BN+ReLU -> L4(32->1)
// BN is training-mode (biased batch stats). Strategy:
//  - Each layer kernel computes z_l = p_{l-1} @ W^T + b, writes z_l (fp32) to a reused
//    __device__ buffer (in-place across layers), and accumulates per-feature sum/sumsq
//    (deterministic tree reduction: registers -> warp shuffle -> smem -> per-CTA partial).
//  - A tiny reduce kernel folds partials into BN scale/shift (a = g*rsqrt(var+eps),
//    c = be - mean*a).
//  - The NEXT layer kernel applies BN+ReLU while staging its input tile into shared
//    memory (so the GEMM inner loop is pure LDS + packed FFMA2).
//  - GEMM inner loop uses fma.rn.f32x2 (FFMA2) for 2x fp32 FMA throughput: each thread
//    owns 16 output features of one row as 8 packed f32x2 accumulators.

#define EPSV 1e-5f
#define NROWS_MAX 2097152
#define GRID_MAIN 2048

__device__ float g_Z[(size_t)NROWS_MAX * 32];     // activation/pre-activation buffer (reused)
__device__ float g_partial[GRID_MAIN * 64];       // per-CTA {sum[32], sumsq[32]}
__device__ float g_bnab[64];                      // a[32], c[32] for the current BN layer

// ---------------- packed f32x2 helpers ----------------
__device__ __forceinline__ unsigned long long pack2(float lo, float hi) {
    unsigned long long r;
    asm("mov.b64 %0, {%1, %2};" : "=l"(r) : "r"(__float_as_uint(lo)), "r"(__float_as_uint(hi)));
    return r;
}
__device__ __forceinline__ void unpack2(unsigned long long v, float& lo, float& hi) {
    unsigned int a, b;
    asm("mov.b64 {%0, %1}, %2;" : "=r"(a), "=r"(b) : "l"(v));
    lo = __uint_as_float(a); hi = __uint_as_float(b);
}
__device__ __forceinline__ unsigned long long splat2(float x) {
    unsigned long long r;
    unsigned int xi = __float_as_uint(x);
    asm("mov.b64 %0, {%1, %1};" : "=l"(r) : "r"(xi));
    return r;
}
__device__ __forceinline__ void fma2(unsigned long long& d, unsigned long long a, unsigned long long b) {
    asm("fma.rn.f32x2 %0, %1, %2, %0;" : "+l"(d) : "l"(a), "l"(b));
}
__device__ __forceinline__ void add2(unsigned long long& d, unsigned long long a) {
    asm("add.rn.f32x2 %0, %0, %1;" : "+l"(d) : "l"(a));
}

// ---------------- layer kernel (KIN -> 32) ----------------
// 256 threads: 128 row-slots x 2 feature-halves. Each thread computes 16 output
// features (8 f32x2 accumulators) for one row per tile. tpc tiles of 128 rows per CTA.
template<int KIN, bool BN>
__global__ void __launch_bounds__(256, 2) layer_kernel(
    const float* __restrict__ xin,          // used only when !BN (layer 1 reads x)
    const float* __restrict__ W,            // [32, KIN] row-major (out-major)
    const float* __restrict__ b,            // [32]
    int tpc)
{
    constexpr int KP = KIN + 1;             // padded stride: conflict-free scalar LDS
    __shared__ unsigned long long sWp[KIN][16];   // sWp[k][jj] = {W[2jj][k], W[2jj+1][k]}
    __shared__ unsigned long long sBp[16];        // packed bias pairs
    __shared__ float sA[32], sC[32];              // BN scale/shift of INPUT layer
    __shared__ float sTile[128 * KP];             // staged (BN+ReLU'd) input rows
    __shared__ unsigned long long sRed[8][16];    // warp-level stat staging

    const int tid = threadIdx.x;

    // stage weights (transposed, packed in output-feature pairs)
    for (int idx = tid; idx < KIN * 16; idx += 256) {
        int k = idx >> 4, jj = idx & 15;
        sWp[k][jj] = pack2(W[(2 * jj) * KIN + k], W[(2 * jj + 1) * KIN + k]);
    }
    if (tid < 16) sBp[tid] = pack2(b[2 * tid], b[2 * tid + 1]);
    if (BN && tid < 32) { sA[tid] = g_bnab[tid]; sC[tid] = g_bnab[32 + tid]; }
    __syncthreads();

    const int half = tid >> 7;      // 0: features 0..15, 1: features 16..31
    const int r    = tid & 127;     // row slot within tile

    unsigned long long vsum[8], vsq[8];
#pragma unroll
    for (int m = 0; m < 8; ++m) { vsum[m] = 0ull; vsq[m] = 0ull; }

    const float* zin = BN ? (const float*)g_Z : xin;

    for (int t = 0; t < tpc; ++t) {
        const long row0 = ((long)blockIdx.x * tpc + t) * 128;

        // ---- stage input tile; apply BN+ReLU of the previous layer during the copy ----
        const float4* src = reinterpret_cast<const float4*>(zin + row0 * KIN);
#pragma unroll
        for (int i = tid; i < (128 * KIN) / 4; i += 256) {
            float4 v = src[i];
            int row = i / (KIN / 4);
            int c0  = (i - row * (KIN / 4)) * 4;
            if (BN) {
                v.x = fmaxf(fmaf(v.x, sA[c0 + 0], sC[c0 + 0]), 0.0f);
                v.y = fmaxf(fmaf(v.y, sA[c0 + 1], sC[c0 + 1]), 0.0f);
                v.z = fmaxf(fmaf(v.z, sA[c0 + 2], sC[c0 + 2]), 0.0f);
                v.w = fmaxf(fmaf(v.w, sA[c0 + 3], sC[c0 + 3]), 0.0f);
            }
            float* dst = &sTile[row * KP + c0];
            dst[0] = v.x; dst[1] = v.y; dst[2] = v.z; dst[3] = v.w;
        }
        __syncthreads();

        // ---- GEMM: 16 output features for row r ----
        unsigned long long zacc[8];
        const unsigned long long* bp = &sBp[half * 8];
#pragma unroll
        for (int m = 0; m < 8; ++m) zacc[m] = bp[m];

        const float* prow = &sTile[r * KP];
#pragma unroll
        for (int k = 0; k < KIN; ++k) {
            unsigned long long pk = splat2(prow[k]);
            const ulonglong2* wp = reinterpret_cast<const ulonglong2*>(&sWp[k][half * 8]);
            ulonglong2 w0 = wp[0], w1 = wp[1], w2 = wp[2], w3 = wp[3];
            fma2(zacc[0], pk, w0.x); fma2(zacc[1], pk, w0.y);
            fma2(zacc[2], pk, w1.x); fma2(zacc[3], pk, w1.y);
            fma2(zacc[4], pk, w2.x); fma2(zacc[5], pk, w2.y);
            fma2(zacc[6], pk, w3.x); fma2(zacc[7], pk, w3.y);
        }

        // ---- write z (pre-BN) ----
        float* orow = g_Z + (row0 + r) * 32 + half * 16;
        ulonglong2* o2 = reinterpret_cast<ulonglong2*>(orow);
#pragma unroll
        for (int mm = 0; mm < 4; ++mm) {
            ulonglong2 v; v.x = zacc[2 * mm]; v.y = zacc[2 * mm + 1];
            o2[mm] = v;
        }

        // ---- accumulate stats of z ----
#pragma unroll
        for (int m = 0; m < 8; ++m) {
            add2(vsum[m], zacc[m]);
            fma2(vsq[m], zacc[m], zacc[m]);
        }
        __syncthreads();   // before sTile is overwritten next tile
    }

    // ---- deterministic stat reduction: warp butterfly -> smem -> per-CTA partial ----
#pragma unroll
    for (int off = 16; off > 0; off >>= 1) {
#pragma unroll
        for (int m = 0; m < 8; ++m) {
            add2(vsum[m], __shfl_xor_sync(0xffffffffu, vsum[m], off));
            add2(vsq[m],  __shfl_xor_sync(0xffffffffu, vsq[m],  off));
        }
    }
    const int w = tid >> 5, lane = tid & 31;
    if (lane == 0) {
#pragma unroll
        for (int m = 0; m < 8; ++m) { sRed[w][m] = vsum[m]; sRed[w][8 + m] = vsq[m]; }
    }
    __syncthreads();
    if (tid < 64) {
        int s = tid >> 5, j = tid & 31;
        int hh = j >> 4, m = (j & 15) >> 1, hi = j & 1;
        float tot = 0.0f;
        for (int w2 = hh * 4; w2 < hh * 4 + 4; ++w2) {
            float lo, hp; unpack2(sRed[w2][s * 8 + m], lo, hp);
            tot += hi ? hp : lo;
        }
        g_partial[blockIdx.x * 64 + tid] = tot;
    }
}

// ---------------- stat reduce + BN coefficient kernel ----------------
__global__ void reduce_kernel(const float* __restrict__ gamma,
                              const float* __restrict__ beta,
                              float invN, int nPart)
{
    __shared__ float sred[16][64];
    __shared__ float stot[64];
    const int tid = threadIdx.x;          // 1024 threads
    const int f = tid & 63, chunk = tid >> 6;
    const int per = nPart >> 4;
    float s = 0.0f;
    const int c0 = chunk * per;
    for (int c = c0; c < c0 + per; ++c) s += g_partial[c * 64 + f];
    sred[chunk][f] = s;
    __syncthreads();
    if (tid < 64) {
        float t = 0.0f;
#pragma unroll
        for (int ch = 0; ch < 16; ++ch) t += sred[ch][tid];
        stot[tid] = t;
    }
    __syncthreads();
    if (tid < 32) {
        float mean = stot[tid] * invN;
        float var  = stot[32 + tid] * invN - mean * mean;
        float a = gamma[tid] * rsqrtf(var + EPSV);
        g_bnab[tid]      = a;
        g_bnab[32 + tid] = beta[tid] - mean * a;
    }
}

// ---------------- final kernel: BN3+ReLU then 32->1 dot ----------------
__global__ void __launch_bounds__(256) final_kernel(
    const float* __restrict__ W4, const float* __restrict__ b4,
    float* __restrict__ out)
{
    __shared__ float sA[32], sC[32], sW[32];
    const int tid = threadIdx.x;
    if (tid < 32) { sA[tid] = g_bnab[tid]; sC[tid] = g_bnab[32 + tid]; sW[tid] = W4[tid]; }
    __syncthreads();
    const long row = (long)blockIdx.x * 256 + tid;
    const float4* zr = reinterpret_cast<const float4*>(g_Z + row * 32);
    float acc = b4[0];
#pragma unroll
    for (int i = 0; i < 8; ++i) {
        float4 v = zr[i];
        int k = i * 4;
        acc = fmaf(fmaxf(fmaf(v.x, sA[k + 0], sC[k + 0]), 0.0f), sW[k + 0], acc);
        acc = fmaf(fmaxf(fmaf(v.y, sA[k + 1], sC[k + 1]), 0.0f), sW[k + 1], acc);
        acc = fmaf(fmaxf(fmaf(v.z, sA[k + 2], sC[k + 2]), 0.0f), sW[k + 2], acc);
        acc = fmaf(fmaxf(fmaf(v.w, sA[k + 3], sC[k + 3]), 0.0f), sW[k + 3], acc);
    }
    out[row] = acc;
}

// ---------------- launcher ----------------
extern "C" void kernel_launch(void* const* d_in, const int* in_sizes, int n_in,
                              void* d_out, int out_size)
{
    const float* x   = (const float*)d_in[0];
    const float* W1  = (const float*)d_in[1];
    const float* b1  = (const float*)d_in[2];
    const float* g1  = (const float*)d_in[3];
    const float* be1 = (const float*)d_in[4];
    const float* W2  = (const float*)d_in[5];
    const float* b2  = (const float*)d_in[6];
    const float* g2  = (const float*)d_in[7];
    const float* be2 = (const float*)d_in[8];
    const float* W3  = (const float*)d_in[9];
    const float* b3  = (const float*)d_in[10];
    const float* g3  = (const float*)d_in[11];
    const float* be3 = (const float*)d_in[12];
    const float* W4  = (const float*)d_in[13];
    const float* b4  = (const float*)d_in[14];

    const int n   = in_sizes[0] / 16;              // 2097152 rows
    const int tpc = n / (GRID_MAIN * 128);         // tiles of 128 rows per CTA
    const float invN = 1.0f / (float)n;

    layer_kernel<16, false><<<GRID_MAIN, 256>>>(x, W1, b1, tpc);
    reduce_kernel<<<1, 1024>>>(g1, be1, invN, GRID_MAIN);

    layer_kernel<32, true><<<GRID_MAIN, 256>>>(x, W2, b2, tpc);
    reduce_kernel<<<1, 1024>>>(g2, be2, invN, GRID_MAIN);

    layer_kernel<32, true><<<GRID_MAIN, 256>>>(x, W3, b3, tpc);
    reduce_kernel<<<1, 1024>>>(g3, be3, invN, GRID_MAIN);

    final_kernel<<<n / 256, 256>>>(W4, b4, (float*)d_out);
}